// round 4
// baseline (speedup 1.0000x reference)
#include <cuda_runtime.h>
#include <math.h>

// Problem constants (fixed by the reference: B=16, N=4096, C=21)
#define BB      16
#define NN      4096
#define CC      21
#define KNN_S   16      // target-dim splits per batch for the KNN kernel
#define PREP_PB 8       // blocks per batch in prep kernel
#define CHUNK   1024    // pred PAIRS per smem tile (=2048 pred points, 32KB)

// Scratch (device globals; no allocation allowed)
__device__ float4 g_pred[BB * NN];            // (px, py, pz, -0.5*|p|^2)
__device__ float4 g_tgt [BB * NN];            // (tx, ty, tz,  |t|^2)
__device__ float  g_dir_part[BB * PREP_PB];   // per-batch dir-loss partial sums
__device__ float  g_knn_part[BB * KNN_S];     // per-batch knn-loss partial sums
__device__ unsigned char g_sym[BB];           // resolved per-batch symmetry flag

typedef unsigned long long ull;

// ---- packed f32x2 helpers (Blackwell sm_100+) ----
__device__ __forceinline__ ull fma2(ull a, ull b, ull c) {
    ull d;
    asm("fma.rn.f32x2 %0, %1, %2, %3;" : "=l"(d) : "l"(a), "l"(b), "l"(c));
    return d;
}
__device__ __forceinline__ ull pack2(float x) {
    ull d;
    asm("mov.b64 %0, {%1, %1};" : "=l"(d) : "r"(__float_as_uint(x)));
    return d;
}
__device__ __forceinline__ float lo2(ull v) { return __uint_as_float((unsigned)(v & 0xffffffffull)); }
__device__ __forceinline__ float hi2(ull v) { return __uint_as_float((unsigned)(v >> 32)); }

// ============================================================================
// Kernel 0: resolve sym flag per batch, once. The reference's sym_flags is a
// numpy BOOL array; the harness upload dtype is unknown (int32 / float32 /
// uint8). Sniff the layout from the data (single thread, deterministic) and
// store the per-batch flag.
//   int32 layout:  every word is 0 or 1
//   float32 layout: every word is 0 or 0x3F800000
//   otherwise: uint8 bytes
// ============================================================================
__global__ void flags_kernel(const void* __restrict__ sym_flags,
                             const int* __restrict__ labels) {
    const int tid = threadIdx.x;   // 32 threads
    __shared__ int mode;           // 0 = word-indexed (i32/f32), 1 = byte-indexed
    if (tid == 0) {
        const unsigned* w = (const unsigned*)sym_flags;
        bool is_i32 = true, is_f32 = true;
        for (int i = 0; i < CC; i++) {
            const unsigned v = w[i];
            if (v > 1u) is_i32 = false;
            if (v != 0u && v != 0x3F800000u) is_f32 = false;
        }
        mode = (is_i32 || is_f32) ? 0 : 1;
    }
    __syncthreads();
    if (tid < BB) {
        const int lb = labels[tid];
        bool s;
        if (mode == 0) s = ((const unsigned*)sym_flags)[lb] != 0u;
        else           s = ((const unsigned char*)sym_flags)[lb] != 0;
        g_sym[tid] = s ? 1 : 0;
    }
}

// ============================================================================
// Kernel 1: rotate points by pred_r / gt_r, store pred/target tuples,
// accumulate the "direct" loss partial sums (sum_n ||pred_n - target_n||).
// grid (BB, PREP_PB), 256 threads; each thread handles 2 points.
// ============================================================================
__global__ void prep_kernel(const float* __restrict__ pred_r,
                            const float* __restrict__ gt_r,
                            const float* __restrict__ points) {
    const int b   = blockIdx.x;
    const int blk = blockIdx.y;
    const int tid = threadIdx.x;

    float R[9], G[9];
#pragma unroll
    for (int i = 0; i < 9; i++) {
        R[i] = pred_r[b * 9 + i];
        G[i] = gt_r[b * 9 + i];
    }

    float dsum = 0.0f;
    const int base = blk * (NN / PREP_PB);   // 512 points per block

#pragma unroll
    for (int k = 0; k < 2; k++) {
        const int n = base + k * 256 + tid;
        const float* p = points + ((long)b * NN + n) * 3;
        const float px = p[0], py = p[1], pz = p[2];

        const float qx = fmaf(R[0], px, fmaf(R[1], py, R[2] * pz));
        const float qy = fmaf(R[3], px, fmaf(R[4], py, R[5] * pz));
        const float qz = fmaf(R[6], px, fmaf(R[7], py, R[8] * pz));
        const float tx = fmaf(G[0], px, fmaf(G[1], py, G[2] * pz));
        const float ty = fmaf(G[3], px, fmaf(G[4], py, G[5] * pz));
        const float tz = fmaf(G[6], px, fmaf(G[7], py, G[8] * pz));

        const float pm = qx * qx + qy * qy + qz * qz;
        const float tn = tx * tx + ty * ty + tz * tz;
        g_pred[b * NN + n] = make_float4(qx, qy, qz, -0.5f * pm);
        g_tgt [b * NN + n] = make_float4(tx, ty, tz, tn);

        const float dx = qx - tx, dy = qy - ty, dz = qz - tz;
        dsum += sqrtf(dx * dx + dy * dy + dz * dz);
    }

    // block reduce (256 threads)
    __shared__ float red[8];
#pragma unroll
    for (int o = 16; o > 0; o >>= 1) dsum += __shfl_down_sync(0xffffffffu, dsum, o);
    if ((tid & 31) == 0) red[tid >> 5] = dsum;
    __syncthreads();
    if (tid < 8) {
        float v = red[tid];
#pragma unroll
        for (int o = 4; o > 0; o >>= 1) v += __shfl_down_sync(0xffu, v, o);
        if (tid == 0) g_dir_part[b * PREP_PB + blk] = v;
    }
}

// ============================================================================
// Kernel 2: brute-force KNN (K=1) for SYMMETRIC batches only.
// grid (BB, KNN_S), 128 threads. Each block: 256 target points, all 4096
// pred points streamed through SMEM in pair-interleaved layout so that the
// packed f32x2 operands fall directly out of LDS.128 register pairs.
// Inner op per pred-pair per target: 3x fma.rn.f32x2 + 2x FMNMX.
// ============================================================================
__global__ void __launch_bounds__(128)
knn_kernel() {
    const int b = blockIdx.x;
    if (!g_sym[b]) return;   // only symmetric batches need KNN

    __shared__ ulonglong2 smA[CHUNK];    // .x = px-pair, .y = py-pair
    __shared__ ulonglong2 smB[CHUNK];    // .x = pz-pair, .y = nh-pair
    __shared__ float red[4];

    const int tid = threadIdx.x;
    const int n0  = blockIdx.y * 256 + tid;     // targets n0 and n0+128

    const float4 t0 = g_tgt[b * NN + n0];
    const float4 t1 = g_tgt[b * NN + n0 + 128];
    const ull tx0 = pack2(t0.x), ty0 = pack2(t0.y), tz0 = pack2(t0.z);
    const ull tx1 = pack2(t1.x), ty1 = pack2(t1.y), tz1 = pack2(t1.z);

    float best0 = -1e30f, best1 = -1e30f;

#pragma unroll
    for (int c = 0; c < NN / (2 * CHUNK); c++) {   // 2 chunks of 2048 preds
        const float4* gp = g_pred + b * NN + c * (2 * CHUNK);

        // cooperative fill: pair-interleave two pred float4s
#pragma unroll
        for (int q = tid; q < CHUNK; q += 128) {
            const float4 a  = gp[2 * q];
            const float4 bb = gp[2 * q + 1];
            ulonglong2 A, Bv;
            A.x  = (ull)__float_as_uint(a.x) | ((ull)__float_as_uint(bb.x) << 32);
            A.y  = (ull)__float_as_uint(a.y) | ((ull)__float_as_uint(bb.y) << 32);
            Bv.x = (ull)__float_as_uint(a.z) | ((ull)__float_as_uint(bb.z) << 32);
            Bv.y = (ull)__float_as_uint(a.w) | ((ull)__float_as_uint(bb.w) << 32);
            smA[q] = A;
            smB[q] = Bv;
        }
        __syncthreads();

#pragma unroll 4
        for (int q = 0; q < CHUNK; q++) {
            const ulonglong2 A  = smA[q];
            const ulonglong2 Bv = smB[q];
            // score = t.p - 0.5*|p|^2, two pred points per packed op
            ull u0 = fma2(tz0, Bv.x, Bv.y);
            u0 = fma2(ty0, A.y, u0);
            u0 = fma2(tx0, A.x, u0);
            ull u1 = fma2(tz1, Bv.x, Bv.y);
            u1 = fma2(ty1, A.y, u1);
            u1 = fma2(tx1, A.x, u1);
            best0 = fmaxf(best0, fmaxf(lo2(u0), hi2(u0)));
            best1 = fmaxf(best1, fmaxf(lo2(u1), hi2(u1)));
        }
        __syncthreads();
    }

    // min d2 = |t|^2 - 2*maxscore ; nearest distance = sqrt(clamp(.,0))
    const float d0 = sqrtf(fmaxf(fmaf(-2.0f, best0, t0.w), 0.0f));
    const float d1 = sqrtf(fmaxf(fmaf(-2.0f, best1, t1.w), 0.0f));
    float s = d0 + d1;

#pragma unroll
    for (int o = 16; o > 0; o >>= 1) s += __shfl_down_sync(0xffffffffu, s, o);
    if ((tid & 31) == 0) red[tid >> 5] = s;
    __syncthreads();
    if (tid < 4) {
        float v = red[tid];
#pragma unroll
        for (int o = 2; o > 0; o >>= 1) v += __shfl_down_sync(0xfu, v, o);
        if (tid == 0) g_knn_part[b * KNN_S + blockIdx.y] = v;
    }
}

// ============================================================================
// Kernel 3: final reduction over batches -> scalar loss.
// ============================================================================
__global__ void final_kernel(const float* __restrict__ mesh_diameter,
                             const int* __restrict__ labels,
                             float* __restrict__ out) {
    const int tid = threadIdx.x;   // 32 threads
    float v = 0.0f;
    if (tid < BB) {
        const int b  = tid;
        const int lb = labels[b];
        float sum = 0.0f;
        if (g_sym[b]) {
#pragma unroll
            for (int s = 0; s < KNN_S; s++) sum += g_knn_part[b * KNN_S + s];
        } else {
#pragma unroll
            for (int k = 0; k < PREP_PB; k++) sum += g_dir_part[b * PREP_PB + k];
        }
        v = sum * (1.0f / NN) / mesh_diameter[lb];
    }
#pragma unroll
    for (int o = 16; o > 0; o >>= 1) v += __shfl_down_sync(0xffffffffu, v, o);
    if (tid == 0) *out = v * (1.0f / BB);
}

// ============================================================================
extern "C" void kernel_launch(void* const* d_in, const int* in_sizes, int n_in,
                              void* d_out, int out_size) {
    const float* pred_r        = (const float*)d_in[0];
    const float* gt_r          = (const float*)d_in[1];
    const float* points        = (const float*)d_in[2];
    const float* mesh_diameter = (const float*)d_in[3];
    const int*   labels        = (const int*)d_in[4];
    const void*  sym_flags     = d_in[5];

    flags_kernel<<<1, 32>>>(sym_flags, labels);
    prep_kernel<<<dim3(BB, PREP_PB), 256>>>(pred_r, gt_r, points);
    knn_kernel<<<dim3(BB, KNN_S), 128>>>();
    final_kernel<<<1, 32>>>(mesh_diameter, labels, (float*)d_out);
}

// round 6
// speedup vs baseline: 1.1117x; 1.1117x over previous
#include <cuda_runtime.h>
#include <math.h>

// Problem constants (fixed by the reference: B=16, N=4096, C=21)
#define BB      16
#define NN      4096
#define CC      21
#define SLICES  16                  // target slices per batch (grid.y)
#define CPAIR   1024                // pred pairs per smem chunk (=2048 points, 32KB)
#define NCHUNK  (NN / (2 * CPAIR))  // 2 chunks

// Scratch (device globals; no allocation allowed)
__device__ float    g_part[BB * SLICES];   // per (batch, slice) partial sums
__device__ unsigned g_done;                // last-block counter (self-resetting)

typedef unsigned long long ull;

// ---- packed f32x2 helpers (sm_100+) ----
__device__ __forceinline__ ull fma2(ull a, ull b, ull c) {
    ull d;
    asm("fma.rn.f32x2 %0, %1, %2, %3;" : "=l"(d) : "l"(a), "l"(b), "l"(c));
    return d;
}
__device__ __forceinline__ ull pack2(float x) {
    ull d;
    asm("mov.b64 %0, {%1, %1};" : "=l"(d) : "r"(__float_as_uint(x)));
    return d;
}
__device__ __forceinline__ ull packab(float a, float b) {
    ull d;
    asm("mov.b64 %0, {%1, %2};" : "=l"(d) : "r"(__float_as_uint(a)), "r"(__float_as_uint(b)));
    return d;
}
__device__ __forceinline__ float lo2(ull v) { return __uint_as_float((unsigned)(v & 0xffffffffull)); }
__device__ __forceinline__ float hi2(ull v) { return __uint_as_float((unsigned)(v >> 32)); }

// sym_flags layout sniff (bool array upcast by harness: int32 / float32 / uint8)
__device__ __forceinline__ int sniff_mode(const void* p) {
    const unsigned* w = (const unsigned*)p;
    bool is_i32 = true, is_f32 = true;
#pragma unroll
    for (int i = 0; i < CC; i++) {
        const unsigned v = w[i];
        if (v > 1u) is_i32 = false;
        if (v != 0u && v != 0x3F800000u) is_f32 = false;
    }
    return (is_i32 || is_f32) ? 0 : 1;   // 0 = word-indexed, 1 = byte-indexed
}
__device__ __forceinline__ bool read_flag(const void* p, int lb, int mode) {
    if (mode == 0) return ((const unsigned*)p)[lb] != 0u;
    return ((const unsigned char*)p)[lb] != 0;
}

// ============================================================================
// ONE kernel. grid (BB, SLICES), 128 threads, 32KB static smem.
//  sym batch:   block streams all 4096 preds of its batch through smem in two
//               2048-point chunks (rotated, pair-interleaved), rotates its own
//               256 targets, runs the packed-FMA score-max loop
//               (min d2 = |t|^2 - 2*max(t.p - |p|^2/2)).
//  non-sym:     block computes the direct-loss partial for its 256-pt slice.
//  last block (atomic counter) reduces all partials -> scalar loss, resets.
// ============================================================================
__global__ void __launch_bounds__(128)
fused_kernel(const float* __restrict__ pred_r,
             const float* __restrict__ gt_r,
             const float* __restrict__ points,
             const float* __restrict__ mesh_diameter,
             const int*   __restrict__ labels,
             const void*  __restrict__ sym_flags,
             float*       __restrict__ out) {
    __shared__ ulonglong2 smA[CPAIR];    // {p0x,p1x} , {p0y,p1y}
    __shared__ ulonglong2 smB[CPAIR];    // {p0z,p1z} , {nh0,nh1}
    __shared__ float red[4];
    __shared__ int   s_sym, s_last;

    const int b   = blockIdx.x;
    const int y   = blockIdx.y;
    const int tid = threadIdx.x;

    if (tid == 0) {
        const int m = sniff_mode(sym_flags);
        s_sym = read_flag(sym_flags, labels[b], m) ? 1 : 0;
    }
    __syncthreads();

    float part = 0.0f;   // this thread's contribution to sum_n dist_n

    if (s_sym) {
        float R[9], G[9];
#pragma unroll
        for (int i = 0; i < 9; i++) {
            R[i] = __ldg(pred_r + b * 9 + i);
            G[i] = __ldg(gt_r   + b * 9 + i);
        }

        // ---- own targets: n0 and n0+128 rotated by gt_r ----
        float tw[2]; ull txp[2], typ[2], tzp[2];
#pragma unroll
        for (int k = 0; k < 2; k++) {
            const int n = y * 256 + k * 128 + tid;
            const float* p = points + ((long)b * NN + n) * 3;
            const float px = p[0], py = p[1], pz = p[2];
            const float tx = fmaf(G[0], px, fmaf(G[1], py, G[2] * pz));
            const float ty = fmaf(G[3], px, fmaf(G[4], py, G[5] * pz));
            const float tz = fmaf(G[6], px, fmaf(G[7], py, G[8] * pz));
            tw[k]  = tx * tx + ty * ty + tz * tz;
            txp[k] = pack2(tx); typ[k] = pack2(ty); tzp[k] = pack2(tz);
        }

        float best0 = -1e30f, best1 = -1e30f;

#pragma unroll
        for (int c = 0; c < NCHUNK; c++) {
            // ---- fill: rotate 2048 preds (1024 pairs) into interleaved smem ----
            const float2* pts2 = (const float2*)(points + ((long)b * NN + c * 2 * CPAIR) * 3);
#pragma unroll
            for (int q = tid; q < CPAIR; q += 128) {
                // pair of points at 2q, 2q+1 : 24 bytes = 3 float2 (8B aligned)
                const float2 f0 = pts2[3 * q + 0];   // p0x p0y
                const float2 f1 = pts2[3 * q + 1];   // p0z p1x
                const float2 f2 = pts2[3 * q + 2];   // p1y p1z

                const float ax = fmaf(R[0], f0.x, fmaf(R[1], f0.y, R[2] * f1.x));
                const float ay = fmaf(R[3], f0.x, fmaf(R[4], f0.y, R[5] * f1.x));
                const float az = fmaf(R[6], f0.x, fmaf(R[7], f0.y, R[8] * f1.x));
                const float bx = fmaf(R[0], f1.y, fmaf(R[1], f2.x, R[2] * f2.y));
                const float by = fmaf(R[3], f1.y, fmaf(R[4], f2.x, R[5] * f2.y));
                const float bz = fmaf(R[6], f1.y, fmaf(R[7], f2.x, R[8] * f2.y));
                const float na = -0.5f * (ax * ax + ay * ay + az * az);
                const float nb = -0.5f * (bx * bx + by * by + bz * bz);

                ulonglong2 A, Bv;
                A.x  = packab(ax, bx);
                A.y  = packab(ay, by);
                Bv.x = packab(az, bz);
                Bv.y = packab(na, nb);
                smA[q] = A;
                smB[q] = Bv;
            }
            __syncthreads();

            // ---- inner loop: max over 1024 pred pairs ----
#pragma unroll 8
            for (int q = 0; q < CPAIR; q++) {
                const ulonglong2 A  = smA[q];
                const ulonglong2 Bv = smB[q];
                ull u0 = fma2(tzp[0], Bv.x, Bv.y);
                u0 = fma2(typ[0], A.y, u0);
                u0 = fma2(txp[0], A.x, u0);
                ull u1 = fma2(tzp[1], Bv.x, Bv.y);
                u1 = fma2(typ[1], A.y, u1);
                u1 = fma2(txp[1], A.x, u1);
                best0 = fmaxf(best0, fmaxf(lo2(u0), hi2(u0)));
                best1 = fmaxf(best1, fmaxf(lo2(u1), hi2(u1)));
            }
            __syncthreads();
        }

        part = sqrtf(fmaxf(fmaf(-2.0f, best0, tw[0]), 0.0f))
             + sqrtf(fmaxf(fmaf(-2.0f, best1, tw[1]), 0.0f));
    } else {
        // ---- direct loss for this 256-point slice ----
        float R[9], G[9];
#pragma unroll
        for (int i = 0; i < 9; i++) {
            R[i] = __ldg(pred_r + b * 9 + i);
            G[i] = __ldg(gt_r   + b * 9 + i);
        }
#pragma unroll
        for (int k = 0; k < 2; k++) {
            const int n = y * 256 + k * 128 + tid;
            const float* p = points + ((long)b * NN + n) * 3;
            const float px = p[0], py = p[1], pz = p[2];
            const float dx = fmaf(R[0] - G[0], px, fmaf(R[1] - G[1], py, (R[2] - G[2]) * pz));
            const float dy = fmaf(R[3] - G[3], px, fmaf(R[4] - G[4], py, (R[5] - G[5]) * pz));
            const float dz = fmaf(R[6] - G[6], px, fmaf(R[7] - G[7], py, (R[8] - G[8]) * pz));
            part += sqrtf(dx * dx + dy * dy + dz * dz);
        }
    }

    // ---- block reduction of part (128 threads) ----
#pragma unroll
    for (int o = 16; o > 0; o >>= 1) part += __shfl_down_sync(0xffffffffu, part, o);
    if ((tid & 31) == 0) red[tid >> 5] = part;
    __syncthreads();
    if (tid == 0) {
        float v = red[0] + red[1] + red[2] + red[3];
        g_part[b * SLICES + y] = v;
        __threadfence();
        const unsigned old = atomicAdd(&g_done, 1u);
        s_last = (old == (unsigned)(BB * SLICES - 1)) ? 1 : 0;
    }
    __syncthreads();

    // ---- last block: final reduction over all (batch, slice) partials ----
    if (s_last) {
        __threadfence();
        if (tid < 32) {
            float v = 0.0f;
            if (tid < BB) {
                float sum = 0.0f;
#pragma unroll
                for (int s = 0; s < SLICES; s++) sum += g_part[tid * SLICES + s];
                v = sum * (1.0f / NN) / __ldg(mesh_diameter + labels[tid]);
            }
#pragma unroll
            for (int o = 16; o > 0; o >>= 1) v += __shfl_down_sync(0xffffffffu, v, o);
            if (tid == 0) {
                *out = v * (1.0f / BB);
                g_done = 0;   // reset for next graph replay (deterministic)
            }
        }
    }
}

// ============================================================================
extern "C" void kernel_launch(void* const* d_in, const int* in_sizes, int n_in,
                              void* d_out, int out_size) {
    const float* pred_r        = (const float*)d_in[0];
    const float* gt_r          = (const float*)d_in[1];
    const float* points        = (const float*)d_in[2];
    const float* mesh_diameter = (const float*)d_in[3];
    const int*   labels        = (const int*)d_in[4];
    const void*  sym_flags     = d_in[5];

    fused_kernel<<<dim3(BB, SLICES), 128>>>(
        pred_r, gt_r, points, mesh_diameter, labels, sym_flags, (float*)d_out);
}

// round 7
// speedup vs baseline: 1.6184x; 1.4558x over previous
#include <cuda_runtime.h>
#include <math.h>

// Problem constants (fixed by the reference: B=16, N=4096, C=21)
#define BB      16
#define NN      4096
#define CC      21
#define SLICES  16                  // target slices per batch (grid.y)
#define PSPLIT  4                   // pred chunks per batch (grid.z)
#define PPTS    (NN / PSPLIT)       // 1024 pred points per chunk
#define CPAIR   (PPTS / 2)          // 512 pred pairs per chunk (16 KB smem)

// Scratch (device globals; zero-initialized, self-resetting for graph replay)
__device__ float    g_best[PSPLIT][BB * NN];   // per-chunk partial max-scores
__device__ float    g_part[BB * SLICES];       // per (batch,slice) loss partials
__device__ unsigned g_cnt [BB * SLICES];       // per-slice sibling counters
__device__ unsigned g_done;                    // global slice counter

typedef unsigned long long ull;

// ---- packed f32x2 helpers (sm_100+) ----
__device__ __forceinline__ ull fma2(ull a, ull b, ull c) {
    ull d;
    asm("fma.rn.f32x2 %0, %1, %2, %3;" : "=l"(d) : "l"(a), "l"(b), "l"(c));
    return d;
}
__device__ __forceinline__ ull pack2(float x) {
    ull d;
    asm("mov.b64 %0, {%1, %1};" : "=l"(d) : "r"(__float_as_uint(x)));
    return d;
}
__device__ __forceinline__ ull packab(float a, float b) {
    ull d;
    asm("mov.b64 %0, {%1, %2};" : "=l"(d) : "r"(__float_as_uint(a)), "r"(__float_as_uint(b)));
    return d;
}
__device__ __forceinline__ float lo2(ull v) { return __uint_as_float((unsigned)(v & 0xffffffffull)); }
__device__ __forceinline__ float hi2(ull v) { return __uint_as_float((unsigned)(v >> 32)); }

// sym_flags layout sniff (bool array upcast by harness: int32 / float32 / uint8)
__device__ __forceinline__ int sniff_mode(const void* p) {
    const unsigned* w = (const unsigned*)p;
    bool is_i32 = true, is_f32 = true;
#pragma unroll
    for (int i = 0; i < CC; i++) {
        const unsigned v = w[i];
        if (v > 1u) is_i32 = false;
        if (v != 0u && v != 0x3F800000u) is_f32 = false;
    }
    return (is_i32 || is_f32) ? 0 : 1;
}
__device__ __forceinline__ bool read_flag(const void* p, int lb, int mode) {
    if (mode == 0) return ((const unsigned*)p)[lb] != 0u;
    return ((const unsigned char*)p)[lb] != 0;
}

// ============================================================================
// ONE kernel. grid (BB, SLICES, PSPLIT), 128 threads, 16KB static smem.
//  sym batch:   each block scans pred chunk z (1024 rotated preds in smem)
//               for its 256 targets; partial max-scores -> g_best[z].
//               Last sibling of the 4 (per-slice counter) combines, sqrts,
//               and writes the slice's loss partial.
//  non-sym:     z==0 block computes the direct loss for its slice; z>0 exit.
//  last slice (global counter) reduces 256 partials -> scalar loss, resets.
// ============================================================================
__global__ void __launch_bounds__(128)
fused_kernel(const float* __restrict__ pred_r,
             const float* __restrict__ gt_r,
             const float* __restrict__ points,
             const float* __restrict__ mesh_diameter,
             const int*   __restrict__ labels,
             const void*  __restrict__ sym_flags,
             float*       __restrict__ out) {
    __shared__ ulonglong2 smA[CPAIR];    // {p0x,p1x} , {p0y,p1y}
    __shared__ ulonglong2 smB[CPAIR];    // {p0z,p1z} , {nh0,nh1}
    __shared__ float red[4];
    __shared__ int   s_sym, s_combine, s_last;

    const int b     = blockIdx.x;
    const int y     = blockIdx.y;
    const int z     = blockIdx.z;
    const int tid   = threadIdx.x;
    const int slice = b * SLICES + y;

    if (tid == 0) {
        const int m = sniff_mode(sym_flags);
        s_sym = read_flag(sym_flags, labels[b], m) ? 1 : 0;
    }
    __syncthreads();

    float part  = 0.0f;        // this thread's contribution to sum_n dist_n
    bool  wrote_part = false;  // whether this block produces g_part[slice]

    if (s_sym) {
        float R[9], G[9];
#pragma unroll
        for (int i = 0; i < 9; i++) {
            R[i] = __ldg(pred_r + b * 9 + i);
            G[i] = __ldg(gt_r   + b * 9 + i);
        }

        // ---- own targets: n0 and n0+128 rotated by gt_r ----
        const int n0 = y * 256 + tid;
        const int n1 = n0 + 128;
        float tw[2]; ull txp[2], typ[2], tzp[2];
#pragma unroll
        for (int k = 0; k < 2; k++) {
            const int n = (k == 0) ? n0 : n1;
            const float* p = points + ((long)b * NN + n) * 3;
            const float px = p[0], py = p[1], pz = p[2];
            const float tx = fmaf(G[0], px, fmaf(G[1], py, G[2] * pz));
            const float ty = fmaf(G[3], px, fmaf(G[4], py, G[5] * pz));
            const float tz = fmaf(G[6], px, fmaf(G[7], py, G[8] * pz));
            tw[k]  = tx * tx + ty * ty + tz * tz;
            txp[k] = pack2(tx); typ[k] = pack2(ty); tzp[k] = pack2(tz);
        }

        // ---- fill: rotate this block's 1024 preds into interleaved smem ----
        const float2* pts2 = (const float2*)(points + ((long)b * NN + z * PPTS) * 3);
#pragma unroll
        for (int q = tid; q < CPAIR; q += 128) {
            const float2 f0 = pts2[3 * q + 0];   // p0x p0y
            const float2 f1 = pts2[3 * q + 1];   // p0z p1x
            const float2 f2 = pts2[3 * q + 2];   // p1y p1z

            const float ax = fmaf(R[0], f0.x, fmaf(R[1], f0.y, R[2] * f1.x));
            const float ay = fmaf(R[3], f0.x, fmaf(R[4], f0.y, R[5] * f1.x));
            const float az = fmaf(R[6], f0.x, fmaf(R[7], f0.y, R[8] * f1.x));
            const float bx = fmaf(R[0], f1.y, fmaf(R[1], f2.x, R[2] * f2.y));
            const float by = fmaf(R[3], f1.y, fmaf(R[4], f2.x, R[5] * f2.y));
            const float bz = fmaf(R[6], f1.y, fmaf(R[7], f2.x, R[8] * f2.y));
            const float na = -0.5f * (ax * ax + ay * ay + az * az);
            const float nb = -0.5f * (bx * bx + by * by + bz * bz);

            ulonglong2 A, Bv;
            A.x  = packab(ax, bx);
            A.y  = packab(ay, by);
            Bv.x = packab(az, bz);
            Bv.y = packab(na, nb);
            smA[q] = A;
            smB[q] = Bv;
        }
        __syncthreads();

        // ---- inner loop: max score over 512 pred pairs ----
        float best0 = -1e30f, best1 = -1e30f;
#pragma unroll 8
        for (int q = 0; q < CPAIR; q++) {
            const ulonglong2 A  = smA[q];
            const ulonglong2 Bv = smB[q];
            ull u0 = fma2(tzp[0], Bv.x, Bv.y);
            u0 = fma2(typ[0], A.y, u0);
            u0 = fma2(txp[0], A.x, u0);
            ull u1 = fma2(tzp[1], Bv.x, Bv.y);
            u1 = fma2(typ[1], A.y, u1);
            u1 = fma2(txp[1], A.x, u1);
            best0 = fmaxf(best0, fmaxf(lo2(u0), hi2(u0)));
            best1 = fmaxf(best1, fmaxf(lo2(u1), hi2(u1)));
        }

        // ---- publish partial maxes; last sibling combines ----
        g_best[z][b * NN + n0] = best0;
        g_best[z][b * NN + n1] = best1;
        __threadfence();
        if (tid == 0) {
            const unsigned old = atomicAdd(&g_cnt[slice], 1u);
            s_combine = (old == PSPLIT - 1) ? 1 : 0;
        }
        __syncthreads();

        if (s_combine) {
            __threadfence();
            float m0 = best0, m1 = best1;
#pragma unroll
            for (int zz = 0; zz < PSPLIT; zz++) {
                if (zz != z) {
                    m0 = fmaxf(m0, g_best[zz][b * NN + n0]);
                    m1 = fmaxf(m1, g_best[zz][b * NN + n1]);
                }
            }
            part = sqrtf(fmaxf(fmaf(-2.0f, m0, tw[0]), 0.0f))
                 + sqrtf(fmaxf(fmaf(-2.0f, m1, tw[1]), 0.0f));
            wrote_part = true;
            if (tid == 0) g_cnt[slice] = 0;   // reset for next graph replay
        }
    } else {
        if (z != 0) return;     // only one sibling does the direct loss
        float R[9], G[9];
#pragma unroll
        for (int i = 0; i < 9; i++) {
            R[i] = __ldg(pred_r + b * 9 + i);
            G[i] = __ldg(gt_r   + b * 9 + i);
        }
#pragma unroll
        for (int k = 0; k < 2; k++) {
            const int n = y * 256 + k * 128 + tid;
            const float* p = points + ((long)b * NN + n) * 3;
            const float px = p[0], py = p[1], pz = p[2];
            const float dx = fmaf(R[0] - G[0], px, fmaf(R[1] - G[1], py, (R[2] - G[2]) * pz));
            const float dy = fmaf(R[3] - G[3], px, fmaf(R[4] - G[4], py, (R[5] - G[5]) * pz));
            const float dz = fmaf(R[6] - G[6], px, fmaf(R[7] - G[7], py, (R[8] - G[8]) * pz));
            part += sqrtf(dx * dx + dy * dy + dz * dz);
        }
        wrote_part = true;
    }

    if (!wrote_part) return;    // sym non-combiner blocks are done

    // ---- block reduction of part (128 threads) -> g_part[slice] ----
#pragma unroll
    for (int o = 16; o > 0; o >>= 1) part += __shfl_down_sync(0xffffffffu, part, o);
    if ((tid & 31) == 0) red[tid >> 5] = part;
    __syncthreads();
    if (tid == 0) {
        g_part[slice] = red[0] + red[1] + red[2] + red[3];
        __threadfence();
        const unsigned old = atomicAdd(&g_done, 1u);
        s_last = (old == (unsigned)(BB * SLICES - 1)) ? 1 : 0;
    }
    __syncthreads();

    // ---- last slice: final reduction over all (batch, slice) partials ----
    if (s_last) {
        __threadfence();
        if (tid < 32) {
            float v = 0.0f;
            if (tid < BB) {
                float sum = 0.0f;
#pragma unroll
                for (int s = 0; s < SLICES; s++) sum += g_part[tid * SLICES + s];
                v = sum * (1.0f / NN) / __ldg(mesh_diameter + labels[tid]);
            }
#pragma unroll
            for (int o = 16; o > 0; o >>= 1) v += __shfl_down_sync(0xffffffffu, v, o);
            if (tid == 0) {
                *out = v * (1.0f / BB);
                g_done = 0;   // reset for next graph replay (deterministic)
            }
        }
    }
}

// ============================================================================
extern "C" void kernel_launch(void* const* d_in, const int* in_sizes, int n_in,
                              void* d_out, int out_size) {
    const float* pred_r        = (const float*)d_in[0];
    const float* gt_r          = (const float*)d_in[1];
    const float* points        = (const float*)d_in[2];
    const float* mesh_diameter = (const float*)d_in[3];
    const int*   labels        = (const int*)d_in[4];
    const void*  sym_flags     = d_in[5];

    fused_kernel<<<dim3(BB, SLICES, PSPLIT), 128>>>(
        pred_r, gt_r, points, mesh_diameter, labels, sym_flags, (float*)d_out);
}

// round 8
// speedup vs baseline: 1.6661x; 1.0295x over previous
#include <cuda_runtime.h>
#include <math.h>

// Problem constants (fixed by the reference: B=16, N=4096, C=21)
#define BB      16
#define NN      4096
#define CC      21
#define SLICES  8                   // target slices per batch (grid.y), 512 targets each
#define PSPLIT  8                   // pred chunks per batch (grid.z)
#define PPTS    (NN / PSPLIT)       // 512 pred points per chunk
#define CPAIR   (PPTS / 2)          // 256 pred pairs per chunk (8 KB smem)
#define NWRITER (BB * SLICES)       // blocks that produce a g_part entry (128)

// Scratch (device globals; zero-initialized, self-resetting for graph replay)
__device__ float    g_best[PSPLIT][BB * NN];   // per-chunk partial max-scores
__device__ float    g_part[NWRITER];           // per (batch,slice) loss partials
__device__ unsigned g_cnt [NWRITER];           // per-slice sibling counters
__device__ unsigned g_done;                    // global writer counter

typedef unsigned long long ull;

// ---- packed f32x2 helpers (sm_100+) ----
__device__ __forceinline__ ull fma2(ull a, ull b, ull c) {
    ull d;
    asm("fma.rn.f32x2 %0, %1, %2, %3;" : "=l"(d) : "l"(a), "l"(b), "l"(c));
    return d;
}
__device__ __forceinline__ ull pack2(float x) {
    ull d;
    asm("mov.b64 %0, {%1, %1};" : "=l"(d) : "r"(__float_as_uint(x)));
    return d;
}
__device__ __forceinline__ ull packab(float a, float b) {
    ull d;
    asm("mov.b64 %0, {%1, %2};" : "=l"(d) : "r"(__float_as_uint(a)), "r"(__float_as_uint(b)));
    return d;
}
__device__ __forceinline__ float lo2(ull v) { return __uint_as_float((unsigned)(v & 0xffffffffull)); }
__device__ __forceinline__ float hi2(ull v) { return __uint_as_float((unsigned)(v >> 32)); }

// sym_flags layout sniff (bool array upcast by harness: int32 / float32 / uint8)
__device__ __forceinline__ int sniff_mode(const void* p) {
    const unsigned* w = (const unsigned*)p;
    bool is_i32 = true, is_f32 = true;
#pragma unroll
    for (int i = 0; i < CC; i++) {
        const unsigned v = w[i];
        if (v > 1u) is_i32 = false;
        if (v != 0u && v != 0x3F800000u) is_f32 = false;
    }
    return (is_i32 || is_f32) ? 0 : 1;
}
__device__ __forceinline__ bool read_flag(const void* p, int lb, int mode) {
    if (mode == 0) return ((const unsigned*)p)[lb] != 0u;
    return ((const unsigned char*)p)[lb] != 0;
}

// ============================================================================
// ONE kernel. grid (BB, SLICES, PSPLIT), 128 threads, 8KB static smem.
//  sym batch:   block scans pred chunk z (512 rotated preds in smem) for its
//               512 targets (4 per thread -> 4 independent FMA chains per
//               LDS pair); partial max-scores -> g_best[z]. Last of the 8
//               siblings (per-slice counter) merges, sqrts, writes the
//               slice's loss partial.
//  non-sym:     z==0 block computes the direct loss for its 512-pt slice.
//  last writer (global counter) reduces 128 partials -> scalar loss, resets.
// ============================================================================
__global__ void __launch_bounds__(128)
fused_kernel(const float* __restrict__ pred_r,
             const float* __restrict__ gt_r,
             const float* __restrict__ points,
             const float* __restrict__ mesh_diameter,
             const int*   __restrict__ labels,
             const void*  __restrict__ sym_flags,
             float*       __restrict__ out) {
    __shared__ ulonglong2 smA[CPAIR];    // {p0x,p1x} , {p0y,p1y}
    __shared__ ulonglong2 smB[CPAIR];    // {p0z,p1z} , {nh0,nh1}
    __shared__ float red[4];
    __shared__ int   s_sym, s_combine, s_last;

    const int b     = blockIdx.x;
    const int y     = blockIdx.y;
    const int z     = blockIdx.z;
    const int tid   = threadIdx.x;
    const int slice = b * SLICES + y;

    if (tid == 0) {
        const int m = sniff_mode(sym_flags);
        s_sym = read_flag(sym_flags, labels[b], m) ? 1 : 0;
    }
    __syncthreads();

    float part  = 0.0f;        // this thread's contribution to sum_n dist_n
    bool  wrote_part = false;  // whether this block produces g_part[slice]

    if (s_sym) {
        float R[9], G[9];
#pragma unroll
        for (int i = 0; i < 9; i++) {
            R[i] = __ldg(pred_r + b * 9 + i);
            G[i] = __ldg(gt_r   + b * 9 + i);
        }

        // ---- own 4 targets rotated by gt_r ----
        float tw[4]; ull txp[4], typ[4], tzp[4];
#pragma unroll
        for (int k = 0; k < 4; k++) {
            const int n = y * 512 + k * 128 + tid;
            const float* p = points + ((long)b * NN + n) * 3;
            const float px = p[0], py = p[1], pz = p[2];
            const float tx = fmaf(G[0], px, fmaf(G[1], py, G[2] * pz));
            const float ty = fmaf(G[3], px, fmaf(G[4], py, G[5] * pz));
            const float tz = fmaf(G[6], px, fmaf(G[7], py, G[8] * pz));
            tw[k]  = tx * tx + ty * ty + tz * tz;
            txp[k] = pack2(tx); typ[k] = pack2(ty); tzp[k] = pack2(tz);
        }

        // ---- fill: rotate this chunk's 512 preds into interleaved smem ----
        const float2* pts2 = (const float2*)(points + ((long)b * NN + z * PPTS) * 3);
#pragma unroll
        for (int q = tid; q < CPAIR; q += 128) {
            const float2 f0 = pts2[3 * q + 0];   // p0x p0y
            const float2 f1 = pts2[3 * q + 1];   // p0z p1x
            const float2 f2 = pts2[3 * q + 2];   // p1y p1z

            const float ax = fmaf(R[0], f0.x, fmaf(R[1], f0.y, R[2] * f1.x));
            const float ay = fmaf(R[3], f0.x, fmaf(R[4], f0.y, R[5] * f1.x));
            const float az = fmaf(R[6], f0.x, fmaf(R[7], f0.y, R[8] * f1.x));
            const float bx = fmaf(R[0], f1.y, fmaf(R[1], f2.x, R[2] * f2.y));
            const float by = fmaf(R[3], f1.y, fmaf(R[4], f2.x, R[5] * f2.y));
            const float bz = fmaf(R[6], f1.y, fmaf(R[7], f2.x, R[8] * f2.y));
            const float na = -0.5f * (ax * ax + ay * ay + az * az);
            const float nb = -0.5f * (bx * bx + by * by + bz * bz);

            ulonglong2 A, Bv;
            A.x  = packab(ax, bx);
            A.y  = packab(ay, by);
            Bv.x = packab(az, bz);
            Bv.y = packab(na, nb);
            smA[q] = A;
            smB[q] = Bv;
        }
        __syncthreads();

        // ---- inner loop: max score over 256 pred pairs, 4 targets ----
        float best[4] = {-1e30f, -1e30f, -1e30f, -1e30f};
#pragma unroll 4
        for (int q = 0; q < CPAIR; q++) {
            const ulonglong2 A  = smA[q];
            const ulonglong2 Bv = smB[q];
#pragma unroll
            for (int k = 0; k < 4; k++) {
                ull u = fma2(tzp[k], Bv.x, Bv.y);
                u = fma2(typ[k], A.y, u);
                u = fma2(txp[k], A.x, u);
                best[k] = fmaxf(best[k], fmaxf(lo2(u), hi2(u)));
            }
        }

        // ---- publish partial maxes; last sibling combines ----
#pragma unroll
        for (int k = 0; k < 4; k++)
            g_best[z][b * NN + y * 512 + k * 128 + tid] = best[k];
        __threadfence();
        if (tid == 0) {
            const unsigned old = atomicAdd(&g_cnt[slice], 1u);
            s_combine = (old == PSPLIT - 1) ? 1 : 0;
        }
        __syncthreads();

        if (s_combine) {
            __threadfence();
#pragma unroll
            for (int k = 0; k < 4; k++) {
                float m = best[k];
                const int idx = b * NN + y * 512 + k * 128 + tid;
#pragma unroll
                for (int zz = 0; zz < PSPLIT; zz++) {
                    if (zz != z) m = fmaxf(m, g_best[zz][idx]);
                }
                part += sqrtf(fmaxf(fmaf(-2.0f, m, tw[k]), 0.0f));
            }
            wrote_part = true;
            if (tid == 0) g_cnt[slice] = 0;   // reset for next graph replay
        }
    } else {
        if (z != 0) return;     // only one sibling does the direct loss
        float R[9], G[9];
#pragma unroll
        for (int i = 0; i < 9; i++) {
            R[i] = __ldg(pred_r + b * 9 + i);
            G[i] = __ldg(gt_r   + b * 9 + i);
        }
#pragma unroll
        for (int k = 0; k < 4; k++) {
            const int n = y * 512 + k * 128 + tid;
            const float* p = points + ((long)b * NN + n) * 3;
            const float px = p[0], py = p[1], pz = p[2];
            const float dx = fmaf(R[0] - G[0], px, fmaf(R[1] - G[1], py, (R[2] - G[2]) * pz));
            const float dy = fmaf(R[3] - G[3], px, fmaf(R[4] - G[4], py, (R[5] - G[5]) * pz));
            const float dz = fmaf(R[6] - G[6], px, fmaf(R[7] - G[7], py, (R[8] - G[8]) * pz));
            part += sqrtf(dx * dx + dy * dy + dz * dz);
        }
        wrote_part = true;
    }

    if (!wrote_part) return;    // sym non-combiner blocks are done

    // ---- block reduction of part (128 threads) -> g_part[slice] ----
#pragma unroll
    for (int o = 16; o > 0; o >>= 1) part += __shfl_down_sync(0xffffffffu, part, o);
    if ((tid & 31) == 0) red[tid >> 5] = part;
    __syncthreads();
    if (tid == 0) {
        g_part[slice] = red[0] + red[1] + red[2] + red[3];
        __threadfence();
        const unsigned old = atomicAdd(&g_done, 1u);
        s_last = (old == (unsigned)(NWRITER - 1)) ? 1 : 0;
    }
    __syncthreads();

    // ---- last writer: final reduction over all (batch, slice) partials ----
    if (s_last) {
        __threadfence();
        if (tid < 32) {
            float v = 0.0f;
            if (tid < BB) {
                float sum = 0.0f;
#pragma unroll
                for (int s = 0; s < SLICES; s++) sum += g_part[tid * SLICES + s];
                v = sum * (1.0f / NN) / __ldg(mesh_diameter + labels[tid]);
            }
#pragma unroll
            for (int o = 16; o > 0; o >>= 1) v += __shfl_down_sync(0xffffffffu, v, o);
            if (tid == 0) {
                *out = v * (1.0f / BB);
                g_done = 0;   // reset for next graph replay (deterministic)
            }
        }
    }
}

// ============================================================================
extern "C" void kernel_launch(void* const* d_in, const int* in_sizes, int n_in,
                              void* d_out, int out_size) {
    const float* pred_r        = (const float*)d_in[0];
    const float* gt_r          = (const float*)d_in[1];
    const float* points        = (const float*)d_in[2];
    const float* mesh_diameter = (const float*)d_in[3];
    const int*   labels        = (const int*)d_in[4];
    const void*  sym_flags     = d_in[5];

    fused_kernel<<<dim3(BB, SLICES, PSPLIT), 128>>>(
        pred_r, gt_r, points, mesh_diameter, labels, sym_flags, (float*)d_out);
}